// round 2
// baseline (speedup 1.0000x reference)
#include <cuda_runtime.h>
#include <cstdint>

// Problem constants (fixed per reference)
#define Bn 8
#define Hn 1080
#define Wn 1920
constexpr int HW  = Hn * Wn;        // 2,073,600
constexpr int BHW = Bn * HW;        // 16,588,800

// Scratch: interleaved accumulator {sum(-fx*w), sum(-fy*w), sum(w), pad}
__device__ float4        g_acc[BHW];       // ~265 MB
__device__ unsigned char g_mask[BHW];      // count>0 flag
__device__ int           g_holes[BHW];     // compacted hole indices
__device__ int           g_hole_count;

// ---------------------------------------------------------------------------
// Vector reduction: one 16B no-return atomic add (3 payload floats + pad).
// ---------------------------------------------------------------------------
__device__ __forceinline__ void red_add_v4(float4* p, float vx, float vy, float w) {
    asm volatile("red.global.add.v4.f32 [%0], {%1, %2, %3, %4};"
                 :: "l"(p), "f"(vx), "f"(vy), "f"(w), "f"(0.0f)
                 : "memory");
}

// ---------------------------------------------------------------------------
// 1) Zero accumulator + hole counter (every replay)
// ---------------------------------------------------------------------------
__global__ void zero_kernel() {
    int i = blockIdx.x * blockDim.x + threadIdx.x;
    g_acc[i] = make_float4(0.f, 0.f, 0.f, 0.f);   // grid sized exactly
    if (i == 0) g_hole_count = 0;
}

// ---------------------------------------------------------------------------
// 2) Forward splat. Grid: (W/128, H, B), block 128 -> zero div/mod.
//    Invalid targets deposit exactly 0 in the reference, so skip them.
// ---------------------------------------------------------------------------
__global__ void splat_kernel(const float* __restrict__ flow,
                             const float* __restrict__ depth) {
    const int x = blockIdx.x * 128 + threadIdx.x;   // [0,1920) exact
    const int y = blockIdx.y;
    const int b = blockIdx.z;

    const int p = y * Wn + x;
    const size_t fbase = (size_t)b * 2 * HW;

    const float fx = __ldg(flow + fbase + p);
    const float fy = __ldg(flow + fbase + HW + p);

    const float x2 = (float)x + fx;
    const float y2 = (float)y + fy;

    if (!(x2 >= 0.0f && x2 <= (float)(Wn - 1) &&
          y2 >= 0.0f && y2 <= (float)(Hn - 1)))
        return;

    const float w  = __ldg(depth + (size_t)b * HW + p);
    const float vx = -fx * w;
    const float vy = -fy * w;

    // floor == trunc (values guaranteed non-negative by validity check)
    const int ixL = (int)x2;
    const int iyT = (int)y2;
    const int ixR = min(ixL + 1, Wn - 1);
    const int iyB = min(iyT + 1, Hn - 1);

    float4* base = g_acc + (size_t)b * HW;
    const int rT = iyT * Wn;
    const int rB = iyB * Wn;
    red_add_v4(base + rT + ixL, vx, vy, w);
    red_add_v4(base + rT + ixR, vx, vy, w);
    red_add_v4(base + rB + ixL, vx, vy, w);
    red_add_v4(base + rB + ixR, vx, vy, w);
}

// ---------------------------------------------------------------------------
// 3) Normalize + hole compaction (warp-aggregated atomics).
//    Grid covers BHW exactly (64800 x 256), no tail.
// ---------------------------------------------------------------------------
__global__ void normalize_kernel(float* __restrict__ out) {
    const int i = blockIdx.x * blockDim.x + threadIdx.x;

    const float4 a   = g_acc[i];
    const float  cnt = a.z;
    const bool   hole = !(cnt > 0.0f);
    const float  inv = 1.0f / (hole ? 1.0f : cnt);

    const int b = i / HW;
    const int p = i - b * HW;

    out[(size_t)b * 2 * HW + p]      = a.x * inv;
    out[(size_t)b * 2 * HW + HW + p] = a.y * inv;
    g_mask[i] = hole ? 0 : 1;

    // Compact hole indices: one atomicAdd per warp.
    const unsigned ballot = __ballot_sync(0xffffffffu, hole);
    if (ballot) {
        const int lane   = threadIdx.x & 31;
        const int leader = __ffs(ballot) - 1;
        int base = 0;
        if (lane == leader) base = atomicAdd(&g_hole_count, __popc(ballot));
        base = __shfl_sync(0xffffffffu, base, leader);
        if (hole) {
            const int rank = __popc(ballot & ((1u << lane) - 1u));
            g_holes[base + rank] = i;
        }
    }
}

// ---------------------------------------------------------------------------
// 4) Hole fill over the compacted list only (~2% of pixels). Each hole walks
//    the 4 axis directions to the nearest filled pixel and averages.
//    Writes only holes, reads only filled pixels -> race-free in-place.
// ---------------------------------------------------------------------------
__global__ void fill_kernel(float* __restrict__ out) {
    const int n      = g_hole_count;
    const int stride = gridDim.x * blockDim.x;

    for (int j = blockIdx.x * blockDim.x + threadIdx.x; j < n; j += stride) {
        const int i = g_holes[j];
        const int b = i / HW;
        const int p = i - b * HW;
        const int y = p / Wn;
        const int x = p - y * Wn;

        const unsigned char* m  = g_mask + (size_t)b * HW;
        float*               o0 = out + (size_t)b * 2 * HW;
        float*               o1 = o0 + HW;

        float sx = 0.f, sy = 0.f;
        int   s  = 0;

        for (int xx = x - 1; xx >= 0; --xx) {            // left
            int q = y * Wn + xx;
            if (m[q]) { sx += o0[q]; sy += o1[q]; s++; break; }
        }
        for (int xx = x + 1; xx < Wn; ++xx) {            // right
            int q = y * Wn + xx;
            if (m[q]) { sx += o0[q]; sy += o1[q]; s++; break; }
        }
        for (int yy = y - 1; yy >= 0; --yy) {            // up
            int q = yy * Wn + x;
            if (m[q]) { sx += o0[q]; sy += o1[q]; s++; break; }
        }
        for (int yy = y + 1; yy < Hn; ++yy) {            // down
            int q = yy * Wn + x;
            if (m[q]) { sx += o0[q]; sy += o1[q]; s++; break; }
        }

        if (s > 0) {
            const float inv = 1.0f / (float)s;
            o0[y * Wn + x] = sx * inv;
            o1[y * Wn + x] = sy * inv;
        }
        // s == 0: out already 0 at holes (count==0 implies acc.xy==0)
    }
}

// ---------------------------------------------------------------------------
// Launch
// ---------------------------------------------------------------------------
extern "C" void kernel_launch(void* const* d_in, const int* in_sizes, int n_in,
                              void* d_out, int out_size) {
    const float* flow  = (const float*)d_in[0];   // (B, 2, H, W) fp32
    const float* depth = (const float*)d_in[1];   // (B, 1, H, W) fp32
    float*       out   = (float*)d_out;           // (B, 2, H, W) fp32

    // BHW == 64800 * 256 exactly
    zero_kernel<<<64800, 256>>>();

    dim3 sgrid(Wn / 128, Hn, Bn);                 // 15 x 1080 x 8, exact
    splat_kernel<<<sgrid, 128>>>(flow, depth);

    normalize_kernel<<<64800, 256>>>(out);

    // ~330K holes expected; grid-stride handles any count.
    fill_kernel<<<2048, 256>>>(out);
}

// round 4
// speedup vs baseline: 1.2804x; 1.2804x over previous
#include <cuda_runtime.h>
#include <cuda_fp16.h>
#include <cstdint>

// Problem constants (fixed per reference)
#define Bn 8
#define Hn 1080
#define Wn 1920
constexpr int HW   = Hn * Wn;          // 2,073,600
constexpr int BHW  = Bn * HW;          // 16,588,800
constexpr int WP   = Wn / 2;           // 960 pair-cells per row
constexpr int LATN = Bn * Hn * WP;     // 8,294,400 pair-cells per lattice

// Pair-cell lattices: each 16B cell = [vx0,vy0,w0,pad | vx1,vy1,w1,pad] (8 x f16)
// Lattice 0 (even parity): pair k covers corners (2k, 2k+1)
// Lattice 1 (odd parity):  pair k covers corners (2k+1, 2k+2)
__device__ float4        g_lat[2 * LATN];   // 265 MB
__device__ unsigned char g_mask[BHW];       // count>0 flag
__device__ int           g_holes[BHW];      // compacted hole indices
__device__ int           g_hole_count;

// --- bit reinterpretation helpers (header-portable) ------------------------
__device__ __forceinline__ unsigned h2_to_u32(__half2 h) {
    union { __half2 h; unsigned u; } cvt;
    cvt.h = h;
    return cvt.u;
}
__device__ __forceinline__ __half2 u32_to_h2(unsigned u) {
    union { unsigned u; __half2 h; } cvt;
    cvt.u = u;
    return cvt.h;
}

// One 16B vectorized f16x2 reduction: deposits (vx,vy,w) to TWO adjacent corners.
__device__ __forceinline__ void red_add_v4_f16x2(float4* p, unsigned r0, unsigned r1,
                                                 unsigned r2, unsigned r3) {
    asm volatile("red.global.add.noftz.v4.f16x2 [%0], {%1, %2, %3, %4};"
                 :: "l"(p), "r"(r0), "r"(r1), "r"(r2), "r"(r3)
                 : "memory");
}

// ---------------------------------------------------------------------------
// 1) Zero both lattices + hole counter (every replay)
// ---------------------------------------------------------------------------
__global__ void zero_kernel() {
    int i = blockIdx.x * blockDim.x + threadIdx.x;   // grid sized exactly 2*LATN
    g_lat[i] = make_float4(0.f, 0.f, 0.f, 0.f);
    if (i == 0) g_hole_count = 0;
}

// ---------------------------------------------------------------------------
// 2) Forward splat: 2 vector REDs per pixel (one per target row), each
//    depositing to both x-adjacent corners at once.
// ---------------------------------------------------------------------------
__global__ void splat_kernel(const float* __restrict__ flow,
                             const float* __restrict__ depth) {
    const int i = blockIdx.x * blockDim.x + threadIdx.x;
    const int b = i / HW;
    const int p = i - b * HW;
    const int y = p / Wn;
    const int x = p - y * Wn;

    const size_t fbase = (size_t)b * 2 * HW;
    const float fx = flow[fbase + p];
    const float fy = flow[fbase + HW + p];

    const float x2 = (float)x + fx;
    const float y2 = (float)y + fy;

    // Invalid pixels deposit exactly 0 in the reference -> skip.
    if (!(x2 >= 0.0f && x2 <= (float)(Wn - 1) &&
          y2 >= 0.0f && y2 <= (float)(Hn - 1)))
        return;

    const float w  = depth[i];
    const float vx = -fx * w;
    const float vy = -fy * w;

    // floor == trunc (non-negative by validity check)
    const int ixL = (int)x2;
    const int iyT = (int)y2;
    const int ixR = min(ixL + 1, Wn - 1);
    const int iyB = min(iyT + 1, Hn - 1);

    // Payload: lo half -> corner ixL, hi half -> corner ixR.
    // ixR==ixL (x2 == W-1 exactly): double the lo payload, zero the hi
    // (rn(2v) == 2*rn(v) in f16, bit-identical to two adds).
    const bool  dup = (ixR == ixL);
    const float m   = dup ? 2.0f : 1.0f;

    const unsigned r0 = h2_to_u32(__floats2half2_rn(vx * m, vy * m));
    const unsigned r1 = h2_to_u32(__floats2half2_rn(w * m, 0.0f));
    const unsigned r2 = dup ? 0u : h2_to_u32(__floats2half2_rn(vx, vy));
    const unsigned r3 = dup ? 0u : h2_to_u32(__floats2half2_rn(w, 0.0f));

    const int s  = ixL & 1;        // lattice parity
    const int kp = ixL >> 1;       // pair index (valid for both parities)

    float4* lat = g_lat + (size_t)s * LATN + (size_t)b * (Hn * WP) + kp;
    red_add_v4_f16x2(lat + iyT * WP, r0, r1, r2, r3);
    red_add_v4_f16x2(lat + iyB * WP, r0, r1, r2, r3);
}

// ---------------------------------------------------------------------------
// 3) Normalize: per output pixel, gather its corner accumulator from the
//    even lattice + odd lattice halves, divide, record mask, compact holes.
// ---------------------------------------------------------------------------
__global__ void normalize_kernel(float* __restrict__ out) {
    const int i = blockIdx.x * blockDim.x + threadIdx.x;
    const int b = i / HW;
    const int p = i - b * HW;
    const int y = p / Wn;
    const int x = p - y * Wn;

    const uint2* lat2 = (const uint2*)g_lat;   // one uint2 = one 8B half-cell
    const size_t rowc = (size_t)b * (Hn * WP) + (size_t)y * WP;

    // Even-lattice contribution: pair x>>1, half x&1
    const uint2 e = lat2[(rowc + (x >> 1)) * 2 + (x & 1)];
    const float2 xyE = __half22float2(u32_to_h2(e.x));
    const float  wE  = __low2float(u32_to_h2(e.y));

    // Odd-lattice contribution: covers x >= 1
    float2 xyO = make_float2(0.f, 0.f);
    float  wO  = 0.f;
    if (x > 0) {
        const int xo = x - 1;
        const uint2 o = lat2[((size_t)LATN + rowc + (xo >> 1)) * 2 + (xo & 1)];
        xyO = __half22float2(u32_to_h2(o.x));
        wO  = __low2float(u32_to_h2(o.y));
    }

    const float cnt  = wE + wO;
    const bool  hole = !(cnt > 0.0f);
    const float inv  = 1.0f / (hole ? 1.0f : cnt);

    out[(size_t)b * 2 * HW + p]      = (xyE.x + xyO.x) * inv;
    out[(size_t)b * 2 * HW + HW + p] = (xyE.y + xyO.y) * inv;
    g_mask[i] = hole ? 0 : 1;

    // Compact hole indices: one atomicAdd per warp.
    const unsigned ballot = __ballot_sync(0xffffffffu, hole);
    if (ballot) {
        const int lane   = threadIdx.x & 31;
        const int leader = __ffs(ballot) - 1;
        int base = 0;
        if (lane == leader) base = atomicAdd(&g_hole_count, __popc(ballot));
        base = __shfl_sync(0xffffffffu, base, leader);
        if (hole) {
            const int rank = __popc(ballot & ((1u << lane) - 1u));
            g_holes[base + rank] = i;
        }
    }
}

// ---------------------------------------------------------------------------
// 4) Hole fill over the compacted list (~2% of pixels): walk 4 axis
//    directions to nearest filled pixel, average. Writes only holes,
//    reads only filled pixels -> race-free in-place.
// ---------------------------------------------------------------------------
__global__ void fill_kernel(float* __restrict__ out) {
    const int n      = g_hole_count;
    const int stride = gridDim.x * blockDim.x;

    for (int j = blockIdx.x * blockDim.x + threadIdx.x; j < n; j += stride) {
        const int i = g_holes[j];
        const int b = i / HW;
        const int p = i - b * HW;
        const int y = p / Wn;
        const int x = p - y * Wn;

        const unsigned char* m  = g_mask + (size_t)b * HW;
        float*               o0 = out + (size_t)b * 2 * HW;
        float*               o1 = o0 + HW;

        float sx = 0.f, sy = 0.f;
        int   s  = 0;

        for (int xx = x - 1; xx >= 0; --xx) {            // left
            int q = y * Wn + xx;
            if (m[q]) { sx += o0[q]; sy += o1[q]; s++; break; }
        }
        for (int xx = x + 1; xx < Wn; ++xx) {            // right
            int q = y * Wn + xx;
            if (m[q]) { sx += o0[q]; sy += o1[q]; s++; break; }
        }
        for (int yy = y - 1; yy >= 0; --yy) {            // up
            int q = yy * Wn + x;
            if (m[q]) { sx += o0[q]; sy += o1[q]; s++; break; }
        }
        for (int yy = y + 1; yy < Hn; ++yy) {            // down
            int q = yy * Wn + x;
            if (m[q]) { sx += o0[q]; sy += o1[q]; s++; break; }
        }

        if (s > 0) {
            const float inv = 1.0f / (float)s;
            o0[y * Wn + x] = sx * inv;
            o1[y * Wn + x] = sy * inv;
        }
        // s == 0: out already 0 at holes (count==0 implies acc.xy==0)
    }
}

// ---------------------------------------------------------------------------
// Launch (R1-proven geometry: 1D grids, 256-thread blocks)
// ---------------------------------------------------------------------------
extern "C" void kernel_launch(void* const* d_in, const int* in_sizes, int n_in,
                              void* d_out, int out_size) {
    const float* flow  = (const float*)d_in[0];   // (B, 2, H, W) fp32
    const float* depth = (const float*)d_in[1];   // (B, 1, H, W) fp32
    float*       out   = (float*)d_out;           // (B, 2, H, W) fp32

    // 2*LATN == BHW == 64800 * 256 exactly
    zero_kernel<<<64800, 256>>>();
    splat_kernel<<<64800, 256>>>(flow, depth);
    normalize_kernel<<<64800, 256>>>(out);
    fill_kernel<<<2048, 256>>>(out);
}

// round 5
// speedup vs baseline: 1.2853x; 1.0039x over previous
#include <cuda_runtime.h>
#include <cuda_fp16.h>
#include <cstdint>

// Problem constants (fixed per reference)
#define Bn 8
#define Hn 1080
#define Wn 1920
constexpr int HW  = Hn * Wn;        // 2,073,600
constexpr int BHW = Bn * HW;        // 16,588,800

// Single accumulator lattice: one 8B slot per corner = [vx, vy, w, pad] (4 x f16).
// Even-x corner pairs are 16B-aligned -> single v4.f16x2 RED covers both.
__device__ uint2         g_cell[BHW];      // 132 MB
__device__ unsigned char g_mask[BHW];      // count>0 flag
__device__ int           g_holes[BHW];     // compacted hole indices
__device__ int           g_hole_count;

// --- bit reinterpretation helpers (header-portable) ------------------------
__device__ __forceinline__ unsigned h2_to_u32(__half2 h) {
    union { __half2 h; unsigned u; } cvt; cvt.h = h; return cvt.u;
}
__device__ __forceinline__ __half2 u32_to_h2(unsigned u) {
    union { unsigned u; __half2 h; } cvt; cvt.u = u; return cvt.h;
}

// 16B vector f16x2 reduction (two adjacent 8B corner slots at once)
__device__ __forceinline__ void red_v4(void* p, unsigned r0, unsigned r1,
                                       unsigned r2, unsigned r3) {
    asm volatile("red.global.add.noftz.v4.f16x2 [%0], {%1, %2, %3, %4};"
                 :: "l"(p), "r"(r0), "r"(r1), "r"(r2), "r"(r3) : "memory");
}
// 8B vector f16x2 reduction (one corner slot)
__device__ __forceinline__ void red_v2(void* p, unsigned r0, unsigned r1) {
    asm volatile("red.global.add.noftz.v2.f16x2 [%0], {%1, %2};"
                 :: "l"(p), "r"(r0), "r"(r1) : "memory");
}

// ---------------------------------------------------------------------------
// 1) Zero lattice + hole counter (every replay). BHW/2 float4 = 32400 x 256.
// ---------------------------------------------------------------------------
__global__ void zero_kernel() {
    int i = blockIdx.x * blockDim.x + threadIdx.x;
    ((float4*)g_cell)[i] = make_float4(0.f, 0.f, 0.f, 0.f);
    if (i == 0) g_hole_count = 0;
}

// ---------------------------------------------------------------------------
// 2) Forward splat: per target row, one 16B RED if the corner pair is aligned
//    (even ixL), else two 8B REDs. Invalid pixels deposit exactly 0 -> skip.
// ---------------------------------------------------------------------------
__global__ void splat_kernel(const float* __restrict__ flow,
                             const float* __restrict__ depth) {
    const int i = blockIdx.x * blockDim.x + threadIdx.x;
    const int b = i / HW;
    const int p = i - b * HW;
    const int y = p / Wn;
    const int x = p - y * Wn;

    const size_t fbase = (size_t)b * 2 * HW;
    const float fx = flow[fbase + p];
    const float fy = flow[fbase + HW + p];

    const float x2 = (float)x + fx;
    const float y2 = (float)y + fy;

    if (!(x2 >= 0.0f && x2 <= (float)(Wn - 1) &&
          y2 >= 0.0f && y2 <= (float)(Hn - 1)))
        return;

    const float w  = depth[i];
    const float vx = -fx * w;
    const float vy = -fy * w;

    // floor == trunc (non-negative by validity check)
    const int ixL = (int)x2;
    const int iyT = (int)y2;
    const int ixR = min(ixL + 1, Wn - 1);
    const int iyB = min(iyT + 1, Hn - 1);

    const unsigned vxy = h2_to_u32(__floats2half2_rn(vx, vy));
    const unsigned wp  = h2_to_u32(__floats2half2_rn(w, 0.0f));

    char* base = (char*)g_cell + (size_t)b * HW * 8;
    const int cT = iyT * Wn;   // corner-row base (corner index units)
    const int cB = iyB * Wn;

    if (!(ixL & 1)) {
        // Even pair: corners (ixL, ixL+1) contiguous & 16B-aligned.
        // (ixL even => ixR == ixL+1 always, since ixL <= W-2.)
        red_v4(base + (size_t)(cT + ixL) * 8, vxy, wp, vxy, wp);
        red_v4(base + (size_t)(cB + ixL) * 8, vxy, wp, vxy, wp);
    } else if (ixR == ixL) {
        // x2 == W-1 exactly (ixL = 1919): both x-corners coincide.
        // rn(2v) == 2*rn(v) in f16 -> doubled payload == two adds.
        const unsigned vxy2 = h2_to_u32(__floats2half2_rn(vx + vx, vy + vy));
        const unsigned wp2  = h2_to_u32(__floats2half2_rn(w + w, 0.0f));
        red_v2(base + (size_t)(cT + ixL) * 8, vxy2, wp2);
        red_v2(base + (size_t)(cB + ixL) * 8, vxy2, wp2);
    } else {
        // Odd pair straddles 16B boundary: two 8B REDs per row.
        red_v2(base + (size_t)(cT + ixL) * 8, vxy, wp);
        red_v2(base + (size_t)(cT + ixR) * 8, vxy, wp);
        red_v2(base + (size_t)(cB + ixL) * 8, vxy, wp);
        red_v2(base + (size_t)(cB + ixR) * 8, vxy, wp);
    }
}

// ---------------------------------------------------------------------------
// 3) Normalize: single 8B load per pixel, divide, mask, compact holes.
// ---------------------------------------------------------------------------
__global__ void normalize_kernel(float* __restrict__ out) {
    const int i = blockIdx.x * blockDim.x + threadIdx.x;

    const uint2  c   = g_cell[i];
    const float2 xy  = __half22float2(u32_to_h2(c.x));
    const float  cnt = __low2float(u32_to_h2(c.y));

    const bool  hole = !(cnt > 0.0f);
    const float inv  = 1.0f / (hole ? 1.0f : cnt);

    const int b = i / HW;
    const int p = i - b * HW;

    out[(size_t)b * 2 * HW + p]      = xy.x * inv;
    out[(size_t)b * 2 * HW + HW + p] = xy.y * inv;
    g_mask[i] = hole ? 0 : 1;

    // Compact hole indices: one atomicAdd per warp.
    const unsigned ballot = __ballot_sync(0xffffffffu, hole);
    if (ballot) {
        const int lane   = threadIdx.x & 31;
        const int leader = __ffs(ballot) - 1;
        int base = 0;
        if (lane == leader) base = atomicAdd(&g_hole_count, __popc(ballot));
        base = __shfl_sync(0xffffffffu, base, leader);
        if (hole) {
            const int rank = __popc(ballot & ((1u << lane) - 1u));
            g_holes[base + rank] = i;
        }
    }
}

// ---------------------------------------------------------------------------
// 4) Hole fill over the compacted list (~2% of pixels): walk 4 axis
//    directions to nearest filled pixel, average. Writes only holes,
//    reads only filled pixels -> race-free in-place.
// ---------------------------------------------------------------------------
__global__ void fill_kernel(float* __restrict__ out) {
    const int n      = g_hole_count;
    const int stride = gridDim.x * blockDim.x;

    for (int j = blockIdx.x * blockDim.x + threadIdx.x; j < n; j += stride) {
        const int i = g_holes[j];
        const int b = i / HW;
        const int p = i - b * HW;
        const int y = p / Wn;
        const int x = p - y * Wn;

        const unsigned char* m  = g_mask + (size_t)b * HW;
        float*               o0 = out + (size_t)b * 2 * HW;
        float*               o1 = o0 + HW;

        float sx = 0.f, sy = 0.f;
        int   s  = 0;

        for (int xx = x - 1; xx >= 0; --xx) {            // left
            int q = y * Wn + xx;
            if (m[q]) { sx += o0[q]; sy += o1[q]; s++; break; }
        }
        for (int xx = x + 1; xx < Wn; ++xx) {            // right
            int q = y * Wn + xx;
            if (m[q]) { sx += o0[q]; sy += o1[q]; s++; break; }
        }
        for (int yy = y - 1; yy >= 0; --yy) {            // up
            int q = yy * Wn + x;
            if (m[q]) { sx += o0[q]; sy += o1[q]; s++; break; }
        }
        for (int yy = y + 1; yy < Hn; ++yy) {            // down
            int q = yy * Wn + x;
            if (m[q]) { sx += o0[q]; sy += o1[q]; s++; break; }
        }

        if (s > 0) {
            const float inv = 1.0f / (float)s;
            o0[y * Wn + x] = sx * inv;
            o1[y * Wn + x] = sy * inv;
        }
        // s == 0: out already 0 at holes (count==0 implies acc.xy==0)
    }
}

// ---------------------------------------------------------------------------
// Launch
// ---------------------------------------------------------------------------
extern "C" void kernel_launch(void* const* d_in, const int* in_sizes, int n_in,
                              void* d_out, int out_size) {
    const float* flow  = (const float*)d_in[0];   // (B, 2, H, W) fp32
    const float* depth = (const float*)d_in[1];   // (B, 1, H, W) fp32
    float*       out   = (float*)d_out;           // (B, 2, H, W) fp32

    zero_kernel<<<32400, 256>>>();        // BHW/2 float4 cells, exact
    splat_kernel<<<64800, 256>>>(flow, depth);
    normalize_kernel<<<64800, 256>>>(out);
    fill_kernel<<<2048, 256>>>(out);
}

// round 6
// speedup vs baseline: 1.3244x; 1.0304x over previous
#include <cuda_runtime.h>
#include <cuda_fp16.h>
#include <cstdint>

// Problem constants (fixed per reference)
#define Bn 8
#define Hn 1080
#define Wn 1920
constexpr int HW   = Hn * Wn;          // 2,073,600
constexpr int BHW  = Bn * HW;          // 16,588,800
constexpr int WP   = Wn / 2;           // 960 pair-cells per row
constexpr int LAT1 = Hn * WP;          // 1,036,800 pair-cells per lattice (per slice)

// Per-slice pair-cell lattices (REUSED for all 8 batches -> stays L2-resident):
// each 16B cell = [vx0,vy0,w0,pad | vx1,vy1,w1,pad] (8 x f16)
// Lattice 0 (even parity): pair k covers corners (2k, 2k+1)
// Lattice 1 (odd parity):  pair k covers corners (2k+1, 2k+2)
__device__ float4        g_lat[2 * LAT1];   // 33.2 MB — fits L2 (126 MB)
__device__ unsigned char g_mask[BHW];       // count>0 flag (whole image)
__device__ int           g_holes[BHW];      // compacted hole indices (global index)
__device__ int           g_hole_count;

// --- bit reinterpretation helpers (header-portable) ------------------------
__device__ __forceinline__ unsigned h2_to_u32(__half2 h) {
    union { __half2 h; unsigned u; } cvt; cvt.h = h; return cvt.u;
}
__device__ __forceinline__ __half2 u32_to_h2(unsigned u) {
    union { unsigned u; __half2 h; } cvt; cvt.u = u; return cvt.h;
}

// One 16B vectorized f16x2 reduction: deposits (vx,vy,w) to TWO adjacent corners.
__device__ __forceinline__ void red_add_v4_f16x2(float4* p, unsigned r0, unsigned r1,
                                                 unsigned r2, unsigned r3) {
    asm volatile("red.global.add.noftz.v4.f16x2 [%0], {%1, %2, %3, %4};"
                 :: "l"(p), "r"(r0), "r"(r1), "r"(r2), "r"(r3) : "memory");
}

// ---------------------------------------------------------------------------
// 1) Zero the slice lattices (+ hole counter once per replay).
//    Grid covers 2*LAT1 == HW exactly (8100 x 256). All writes are L2 hits.
// ---------------------------------------------------------------------------
__global__ void zero_kernel(int reset_counter) {
    int i = blockIdx.x * blockDim.x + threadIdx.x;
    g_lat[i] = make_float4(0.f, 0.f, 0.f, 0.f);
    if (reset_counter && i == 0) g_hole_count = 0;
}

// ---------------------------------------------------------------------------
// 2) Forward splat for ONE batch slice: 2 vector REDs per pixel (one per
//    target row), each depositing to both x-adjacent corners at once.
//    flow/depth pointers are pre-offset to this batch.
// ---------------------------------------------------------------------------
__global__ void splat_kernel(const float* __restrict__ flow,
                             const float* __restrict__ depth) {
    const int p = blockIdx.x * blockDim.x + threadIdx.x;   // [0, HW)
    const int y = p / Wn;
    const int x = p - y * Wn;

    const float fx = flow[p];
    const float fy = flow[HW + p];

    const float x2 = (float)x + fx;
    const float y2 = (float)y + fy;

    // Invalid pixels deposit exactly 0 in the reference -> skip.
    if (!(x2 >= 0.0f && x2 <= (float)(Wn - 1) &&
          y2 >= 0.0f && y2 <= (float)(Hn - 1)))
        return;

    const float w  = depth[p];
    const float vx = -fx * w;
    const float vy = -fy * w;

    // floor == trunc (non-negative by validity check)
    const int ixL = (int)x2;
    const int iyT = (int)y2;
    const int ixR = min(ixL + 1, Wn - 1);
    const int iyB = min(iyT + 1, Hn - 1);

    // Payload: lo half -> corner ixL, hi half -> corner ixR.
    // ixR==ixL (x2 == W-1 exactly): double lo payload, zero hi
    // (rn(2v) == 2*rn(v) in f16, bit-identical to two adds).
    const bool  dup = (ixR == ixL);
    const float m   = dup ? 2.0f : 1.0f;

    const unsigned r0 = h2_to_u32(__floats2half2_rn(vx * m, vy * m));
    const unsigned r1 = h2_to_u32(__floats2half2_rn(w * m, 0.0f));
    const unsigned r2 = dup ? 0u : h2_to_u32(__floats2half2_rn(vx, vy));
    const unsigned r3 = dup ? 0u : h2_to_u32(__floats2half2_rn(w, 0.0f));

    const int s  = ixL & 1;        // lattice parity
    const int kp = ixL >> 1;       // pair index

    float4* lat = g_lat + (size_t)s * LAT1 + kp;
    red_add_v4_f16x2(lat + iyT * WP, r0, r1, r2, r3);
    red_add_v4_f16x2(lat + iyB * WP, r0, r1, r2, r3);
}

// ---------------------------------------------------------------------------
// 3) Normalize ONE batch slice: gather even+odd lattice halves per pixel,
//    divide, write out slice, record mask, compact holes (global indices).
//    out pointer pre-offset to this batch; gbase = b*HW.
// ---------------------------------------------------------------------------
__global__ void normalize_kernel(float* __restrict__ out, int gbase) {
    const int p = blockIdx.x * blockDim.x + threadIdx.x;   // [0, HW)
    const int y = p / Wn;
    const int x = p - y * Wn;

    const uint2* lat2 = (const uint2*)g_lat;   // one uint2 = one 8B half-cell
    const size_t rowc = (size_t)y * WP;

    // Even-lattice contribution: pair x>>1, half x&1
    const uint2 e = lat2[(rowc + (x >> 1)) * 2 + (x & 1)];
    const float2 xyE = __half22float2(u32_to_h2(e.x));
    const float  wE  = __low2float(u32_to_h2(e.y));

    // Odd-lattice contribution: covers x >= 1
    float2 xyO = make_float2(0.f, 0.f);
    float  wO  = 0.f;
    if (x > 0) {
        const int xo = x - 1;
        const uint2 o = lat2[((size_t)LAT1 + rowc + (xo >> 1)) * 2 + (xo & 1)];
        xyO = __half22float2(u32_to_h2(o.x));
        wO  = __low2float(u32_to_h2(o.y));
    }

    const float cnt  = wE + wO;
    const bool  hole = !(cnt > 0.0f);
    const float inv  = 1.0f / (hole ? 1.0f : cnt);

    out[p]      = (xyE.x + xyO.x) * inv;
    out[HW + p] = (xyE.y + xyO.y) * inv;
    g_mask[gbase + p] = hole ? 0 : 1;

    // Compact hole indices: one atomicAdd per warp.
    const unsigned ballot = __ballot_sync(0xffffffffu, hole);
    if (ballot) {
        const int lane   = threadIdx.x & 31;
        const int leader = __ffs(ballot) - 1;
        int base = 0;
        if (lane == leader) base = atomicAdd(&g_hole_count, __popc(ballot));
        base = __shfl_sync(0xffffffffu, base, leader);
        if (hole) {
            const int rank = __popc(ballot & ((1u << lane) - 1u));
            g_holes[base + rank] = gbase + p;
        }
    }
}

// ---------------------------------------------------------------------------
// 4) Hole fill over the compacted list (~2% of pixels): walk 4 axis
//    directions to nearest filled pixel, average. Writes only holes,
//    reads only filled pixels -> race-free in-place.
// ---------------------------------------------------------------------------
__global__ void fill_kernel(float* __restrict__ out) {
    const int n      = g_hole_count;
    const int stride = gridDim.x * blockDim.x;

    for (int j = blockIdx.x * blockDim.x + threadIdx.x; j < n; j += stride) {
        const int i = g_holes[j];
        const int b = i / HW;
        const int p = i - b * HW;
        const int y = p / Wn;
        const int x = p - y * Wn;

        const unsigned char* m  = g_mask + (size_t)b * HW;
        float*               o0 = out + (size_t)b * 2 * HW;
        float*               o1 = o0 + HW;

        float sx = 0.f, sy = 0.f;
        int   s  = 0;

        for (int xx = x - 1; xx >= 0; --xx) {            // left
            int q = y * Wn + xx;
            if (m[q]) { sx += o0[q]; sy += o1[q]; s++; break; }
        }
        for (int xx = x + 1; xx < Wn; ++xx) {            // right
            int q = y * Wn + xx;
            if (m[q]) { sx += o0[q]; sy += o1[q]; s++; break; }
        }
        for (int yy = y - 1; yy >= 0; --yy) {            // up
            int q = yy * Wn + x;
            if (m[q]) { sx += o0[q]; sy += o1[q]; s++; break; }
        }
        for (int yy = y + 1; yy < Hn; ++yy) {            // down
            int q = yy * Wn + x;
            if (m[q]) { sx += o0[q]; sy += o1[q]; s++; break; }
        }

        if (s > 0) {
            const float inv = 1.0f / (float)s;
            o0[y * Wn + x] = sx * inv;
            o1[y * Wn + x] = sy * inv;
        }
        // s == 0: out already 0 at holes (count==0 implies acc.xy==0)
    }
}

// ---------------------------------------------------------------------------
// Launch: per-batch slice pipeline through the L2-resident scratch.
// ---------------------------------------------------------------------------
extern "C" void kernel_launch(void* const* d_in, const int* in_sizes, int n_in,
                              void* d_out, int out_size) {
    const float* flow  = (const float*)d_in[0];   // (B, 2, H, W) fp32
    const float* depth = (const float*)d_in[1];   // (B, 1, H, W) fp32
    float*       out   = (float*)d_out;           // (B, 2, H, W) fp32

    // HW == 8100 * 256 exactly
    for (int b = 0; b < Bn; ++b) {
        zero_kernel<<<8100, 256>>>(b == 0 ? 1 : 0);
        splat_kernel<<<8100, 256>>>(flow + (size_t)b * 2 * HW,
                                    depth + (size_t)b * HW);
        normalize_kernel<<<8100, 256>>>(out + (size_t)b * 2 * HW, b * HW);
    }
    fill_kernel<<<2048, 256>>>(out);
}